// round 5
// baseline (speedup 1.0000x reference)
#include <cuda_runtime.h>

// Persistent grid-stride single-pass reduction. Exactly SMs*5 CTAs; each
// loops over 256-row tiles (coalesced float4 staging through smem, 8-deep
// LDG.128 front batch, __ldcs streaming). No wave transitions, one atomic
// per CTA.

#define RPB 256
#define MU_PRIOR  0.6447f
#define LOGDET_SA 4.76770561517f   // 3*log(4.9)
#define INV49     (1.0f/4.9f)

#define W0 (1.0f/(0.0015f *0.0015f ))
#define W1 (1.0f/(0.0012f *0.0012f ))
#define W2 (1.0f/(0.001f  *0.001f  ))
#define W3 (1.0f/(0.00086f*0.00086f))
#define W4 (1.0f/(0.00057f*0.00057f))

__constant__ float c_W5[5] = {W0, W1, W2, W3, W4};
__constant__ float c_W20[20] = {
    W0, W1, W2, W3,
    W1, W2, W3, W4,
    W2, W3, W4, W0,
    W3, W4, W0, W1,
    W4, W0, W1, W2
};

__device__ float    g_partial = 0.f;
__device__ unsigned g_count   = 0u;

__device__ __forceinline__ float wssq(float4 a, float4 b, int p) {
    const float* w = &c_W20[p * 4];
    float acc, d;
    d = a.x - b.x; acc  = w[0] * d * d;
    d = a.y - b.y; acc += w[1] * d * d;
    d = a.z - b.z; acc += w[2] * d * d;
    d = a.w - b.w; acc += w[3] * d * d;
    return acc;
}

__device__ __forceinline__ void stage_one(float4 P, float4 Q, float4 Z, float4 C,
                                          float4* sd4, float4* sf4, float4* sc4, int idx) {
    float4 dsq, fin; float d;
    d = P.x - Q.x; dsq.x = d * d; fin.x = (Z.x == Z.x) ? 1.f : 0.f;
    d = P.y - Q.y; dsq.y = d * d; fin.y = (Z.y == Z.y) ? 1.f : 0.f;
    d = P.z - Q.z; dsq.z = d * d; fin.z = (Z.z == Z.z) ? 1.f : 0.f;
    d = P.w - Q.w; dsq.w = d * d; fin.w = (Z.w == Z.w) ? 1.f : 0.f;
    sd4[idx] = dsq; sf4[idx] = fin; sc4[idx] = C;
}

__global__ void __launch_bounds__(256, 5)
loss_kernel(const float4* __restrict__ pred4, const float4* __restrict__ yobs4,
            const float4* __restrict__ rrs4,  const float4* __restrict__ rrsp4,
            const float4* __restrict__ nan4,  const float4* __restrict__ cov4,
            const float4* __restrict__ mu4,   const float*  __restrict__ prm,
            float* __restrict__ out,
            int n, int ntiles, int np,
            float s_rrs, float s_obs, float s_dk, float s_mu)
{
    __shared__ __align__(16) float s_dy2[RPB * 9];
    __shared__ __align__(16) float s_fin[RPB * 9];
    __shared__ __align__(16) float s_cov[RPB * 9];
    __shared__ float wsum[8];

    const int tid = threadIdx.x;
    float4* sd4 = reinterpret_cast<float4*>(s_dy2);
    float4* sf4 = reinterpret_cast<float4*>(s_fin);
    float4* sc4 = reinterpret_cast<float4*>(s_cov);

    float tot = 0.f;

    // ---- params l2 (block 0 only) ----
    if (blockIdx.x == 0) {
        float acc = 0.f;
        for (int i = tid; i < np; i += 256) {
            float d = prm[i] - 1.f;
            acc += d * d;
        }
        tot += acc / (float)np;
    }

    for (int t = blockIdx.x; t < ntiles; t += gridDim.x) {
        const int row0 = t * RPB;
        const int rows = min(RPB, n - row0);

        if (rows == RPB) {
            // ============ FAST PATH: full 256-row tile ============
            const float4* p4 = pred4 + row0 * 9 / 4;   // 576*t
            const float4* q4 = yobs4 + row0 * 9 / 4;
            const float4* z4 = nan4  + row0 * 9 / 4;
            const float4* c4 = cov4  + row0 * 9 / 4;
            const float4* a4 = rrs4  + row0 * 5 / 4;   // 320*t
            const float4* e4 = rrsp4 + row0 * 5 / 4;
            const float4* m4 = mu4   + row0 * 3 / 4;   // 192*t

            // ---- 8-deep front batch of 9-wide streams ----
            float4 P0 = __ldcs(p4 + tid);       float4 P1 = __ldcs(p4 + tid + 256);
            float4 Q0 = __ldcs(q4 + tid);       float4 Q1 = __ldcs(q4 + tid + 256);
            float4 Z0 = __ldcs(z4 + tid);       float4 Z1 = __ldcs(z4 + tid + 256);
            float4 C0 = __ldcs(c4 + tid);       float4 C1 = __ldcs(c4 + tid + 256);
            stage_one(P0, Q0, Z0, C0, sd4, sf4, sc4, tid);
            stage_one(P1, Q1, Z1, C1, sd4, sf4, sc4, tid + 256);
            if (tid < 64) {
                float4 P2 = __ldcs(p4 + tid + 512);
                float4 Q2 = __ldcs(q4 + tid + 512);
                float4 Z2 = __ldcs(z4 + tid + 512);
                float4 C2 = __ldcs(c4 + tid + 512);
                stage_one(P2, Q2, Z2, C2, sd4, sf4, sc4, tid + 512);
            }

            // ---- flat rrs weighted SSQ ----
            {
                float4 A0 = __ldcs(a4 + tid);
                float4 E0 = __ldcs(e4 + tid);
                int p0 = (int)((unsigned)(4 * tid) % 5u);
                tot += wssq(A0, E0, p0) * s_rrs;
                if (tid < 64) {
                    float4 A1 = __ldcs(a4 + tid + 256);
                    float4 E1 = __ldcs(e4 + tid + 256);
                    int p1 = (int)((unsigned)(4 * tid + 4) % 5u);  // +1024 ≡ +4 (mod 5)
                    tot += wssq(A1, E1, p1) * s_rrs;
                }
            }

            // ---- flat mu SSQ ----
            if (tid < 192) {
                float4 M0 = __ldcs(m4 + tid);
                float acc, d;
                d = M0.x - MU_PRIOR; acc  = d * d;
                d = M0.y - MU_PRIOR; acc += d * d;
                d = M0.z - MU_PRIOR; acc += d * d;
                d = M0.w - MU_PRIOR; acc += d * d;
                tot += acc * s_mu;
            }

            __syncthreads();

            // ---- per-row math (1 row/thread, stride-9 = conflict-free) ----
            {
                const float* dy = &s_dy2[tid * 9];
                const float* fi = &s_fin[tid * 9];
                const float* cm = &s_cov[tid * 9];

                float rsum = 0.f, lens = 0.f;
                #pragma unroll
                for (int i = 0; i < 9; i++) { rsum += dy[i]; lens += fi[i]; }
                tot += __fdividef(rsum, lens) * s_obs;

                float m0 = cm[0], m1 = cm[1], m2 = cm[2];
                float m3 = cm[3], m4 = cm[4], m5 = cm[5];
                float m6 = cm[6], m7 = cm[7], m8 = cm[8];
                float tr  = m0 + m4 + m8;
                float det = m0 * (m4 * m8 - m5 * m7)
                          - m1 * (m3 * m8 - m5 * m6)
                          + m2 * (m3 * m7 - m4 * m6);
                tot += ((LOGDET_SA - __logf(det)) + tr * INV49) * s_dk;
            }
        } else {
            // ============ SLOW PATH: final partial tile ============
            {
                const int base = row0 * 5;
                const int nf   = rows * 5;
                const float* af = (const float*)rrs4;
                const float* ef = (const float*)rrsp4;
                float acc = 0.f;
                for (int g = base + tid; g < base + nf; g += 256) {
                    float d = af[g] - ef[g];
                    acc += c_W5[(unsigned)g % 5u] * d * d;
                }
                tot += acc * s_rrs;
            }
            {
                const int base = row0 * 3;
                const int nf   = rows * 3;
                const float* mf = (const float*)mu4;
                float acc = 0.f;
                for (int g = base + tid; g < base + nf; g += 256) {
                    float d = mf[g] - MU_PRIOR;
                    acc += d * d;
                }
                tot += acc * s_mu;
            }
            {
                const int base = row0 * 9;
                const int nf   = rows * 9;
                const float* pf = (const float*)pred4;
                const float* qf = (const float*)yobs4;
                const float* zf = (const float*)nan4;
                const float* cf = (const float*)cov4;
                for (int j = tid; j < nf; j += 256) {
                    float d = pf[base + j] - qf[base + j];
                    s_dy2[j] = d * d;
                    float z = zf[base + j];
                    s_fin[j] = (z == z) ? 1.f : 0.f;
                    s_cov[j] = cf[base + j];
                }
            }
            __syncthreads();
            for (int r = tid; r < rows; r += 256) {
                const float* dy = &s_dy2[r * 9];
                const float* fi = &s_fin[r * 9];
                const float* cm = &s_cov[r * 9];
                float rsum = 0.f, lens = 0.f;
                #pragma unroll
                for (int i = 0; i < 9; i++) { rsum += dy[i]; lens += fi[i]; }
                tot += __fdividef(rsum, lens) * s_obs;
                float m0 = cm[0], m1 = cm[1], m2 = cm[2];
                float m3 = cm[3], m4 = cm[4], m5 = cm[5];
                float m6 = cm[6], m7 = cm[7], m8 = cm[8];
                float tr  = m0 + m4 + m8;
                float det = m0 * (m4 * m8 - m5 * m7)
                          - m1 * (m3 * m8 - m5 * m6)
                          + m2 * (m3 * m7 - m4 * m6);
                tot += ((LOGDET_SA - __logf(det)) + tr * INV49) * s_dk;
            }
        }

        __syncthreads();   // smem reused by next tile
    }

    // ---- block reduction + grid finalize ----
    #pragma unroll
    for (int o = 16; o > 0; o >>= 1) tot += __shfl_down_sync(0xffffffffu, tot, o);
    int lane = tid & 31;
    int wid  = tid >> 5;
    if (lane == 0) wsum[wid] = tot;
    __syncthreads();
    if (wid == 0) {
        float v = (lane < 8) ? wsum[lane] : 0.f;
        #pragma unroll
        for (int o = 4; o > 0; o >>= 1) v += __shfl_down_sync(0xffffffffu, v, o);
        if (lane == 0) {
            atomicAdd(&g_partial, v);
            __threadfence();
            unsigned c = atomicAdd(&g_count, 1u);
            if (c == gridDim.x - 1u) {
                __threadfence();
                float total = atomicExch(&g_partial, 0.f);  // read + reset for replay
                out[0] = total;
                g_count = 0u;
            }
        }
    }
}

extern "C" void kernel_launch(void* const* d_in, const int* in_sizes, int n_in,
                              void* d_out, int out_size)
{
    const float4* pred = (const float4*)d_in[0];
    const float4* yobs = (const float4*)d_in[1];
    const float4* rrs  = (const float4*)d_in[2];
    const float4* rrsp = (const float4*)d_in[3];
    const float4* nana = (const float4*)d_in[4];
    const float4* cov  = (const float4*)d_in[5];
    const float4* mu   = (const float4*)d_in[6];
    const float*  prm  = (const float*)d_in[7];
    float* out = (float*)d_out;

    int n  = in_sizes[0] / 9;
    int np = in_sizes[7];
    int ntiles = (n + RPB - 1) / RPB;

    int dev = 0, sms = 148;
    cudaGetDevice(&dev);
    cudaDeviceGetAttribute(&sms, cudaDevAttrMultiProcessorCount, dev);
    int nblocks = sms * 5;                 // 5 CTAs/SM resident (reg/smem fit)
    if (nblocks > ntiles) nblocks = ntiles;

    double dn = (double)n;
    float s_rrs = (float)(1.0 / (5.0 * dn));
    float s_obs = (float)(10.0 / dn);
    float s_dk  = (float)(0.5 / dn);
    float s_mu  = (float)(0.5 / (4.9 * 3.0 * dn));

    loss_kernel<<<nblocks, 256>>>(pred, yobs, rrs, rrsp, nana, cov, mu, prm,
                                  out, n, ntiles, np,
                                  s_rrs, s_obs, s_dk, s_mu);
}

// round 6
// speedup vs baseline: 1.0617x; 1.0617x over previous
#include <cuda_runtime.h>
#include <cstdint>

// Persistent CTAs + cp.async.bulk (UBLKCP) 4-stage smem ring.
// 128-row tiles; 7 contiguous bulk copies per tile (25,088 B) tracked by one
// mbarrier expect_tx. Consumers compute directly from smem. One atomic/CTA.

#define ROWS_T   128
#define NST      4
#define THREADS  256

#define OFF_P 0        // pred : 1152 floats (4608 B)
#define OFF_Q 1152     // yobs
#define OFF_Z 2304     // nan
#define OFF_C 3456     // cov
#define OFF_A 4608     // rrs  : 640 floats (2560 B)
#define OFF_E 5248     // rrs_pred
#define OFF_M 5888     // mu   : 384 floats (1536 B)
#define STAGE_FLOATS 6272
#define STAGE_BYTES  25088

#define MU_PRIOR  0.6447f
#define LOGDET_SA 4.76770561517f   // 3*log(4.9)
#define INV49     (1.0f/4.9f)

#define W0 (1.0f/(0.0015f *0.0015f ))
#define W1 (1.0f/(0.0012f *0.0012f ))
#define W2 (1.0f/(0.001f  *0.001f  ))
#define W3 (1.0f/(0.00086f*0.00086f))
#define W4 (1.0f/(0.00057f*0.00057f))

__constant__ float c_W5[5] = {W0, W1, W2, W3, W4};
__constant__ float c_W20[20] = {
    W0, W1, W2, W3,
    W1, W2, W3, W4,
    W2, W3, W4, W0,
    W3, W4, W0, W1,
    W4, W0, W1, W2
};

__device__ float    g_partial = 0.f;
__device__ unsigned g_count   = 0u;

__device__ __forceinline__ uint32_t s2u(const void* p) {
    return (uint32_t)__cvta_generic_to_shared(p);
}

__device__ __forceinline__ void mbar_init(uint32_t addr, unsigned cnt) {
    asm volatile("mbarrier.init.shared.b64 [%0], %1;" :: "r"(addr), "r"(cnt) : "memory");
}

__device__ __forceinline__ void mbar_expect_tx(uint32_t addr, unsigned bytes) {
    asm volatile("mbarrier.arrive.expect_tx.shared.b64 _, [%0], %1;"
                 :: "r"(addr), "r"(bytes) : "memory");
}

__device__ __forceinline__ void mbar_wait(uint32_t addr, unsigned parity) {
    asm volatile(
        "{\n\t.reg .pred P;\n\t"
        "LW_%=:\n\t"
        "mbarrier.try_wait.parity.acquire.cta.shared::cta.b64 P, [%0], %1, 0x989680;\n\t"
        "@P bra.uni LD_%=;\n\t"
        "bra.uni LW_%=;\n\t"
        "LD_%=:\n\t}"
        :: "r"(addr), "r"(parity) : "memory");
}

__device__ __forceinline__ void bulk_cp(uint32_t dst, const void* src,
                                        unsigned bytes, uint32_t mbar) {
    asm volatile(
        "cp.async.bulk.shared::cluster.global.mbarrier::complete_tx::bytes "
        "[%0], [%1], %2, [%3];"
        :: "r"(dst), "l"(src), "r"(bytes), "r"(mbar) : "memory");
}

__device__ __forceinline__ float wssq(float4 a, float4 b, int p) {
    const float* w = &c_W20[p * 4];
    float acc, d;
    d = a.x - b.x; acc  = w[0] * d * d;
    d = a.y - b.y; acc += w[1] * d * d;
    d = a.z - b.z; acc += w[2] * d * d;
    d = a.w - b.w; acc += w[3] * d * d;
    return acc;
}

__global__ void __launch_bounds__(THREADS, 2)
loss_kernel(const float* __restrict__ pred, const float* __restrict__ yobs,
            const float* __restrict__ rrs,  const float* __restrict__ rrsp,
            const float* __restrict__ nana, const float* __restrict__ cov,
            const float* __restrict__ mu,   const float* __restrict__ prm,
            float* __restrict__ out,
            int n, int ntiles, int np,
            float s_rrs, float s_obs, float s_dk, float s_mu)
{
    extern __shared__ __align__(16) float smem[];    // NST * STAGE_FLOATS
    __shared__ __align__(8) uint64_t mbar_store[NST];
    __shared__ float wsum[8];

    const int tid = threadIdx.x;
    const int G   = gridDim.x;

    uint32_t mb[NST];
    #pragma unroll
    for (int s = 0; s < NST; s++) mb[s] = s2u(&mbar_store[s]);

    if (tid == 0) {
        #pragma unroll
        for (int s = 0; s < NST; s++) mbar_init(mb[s], 1);
        asm volatile("fence.proxy.async.shared::cta;" ::: "memory");
    }
    __syncthreads();

    float tot = 0.f;

    // ---- params l2 (block 0 only) ----
    if (blockIdx.x == 0) {
        float acc = 0.f;
        for (int i = tid; i < np; i += THREADS) {
            float d = prm[i] - 1.f;
            acc += d * d;
        }
        tot += acc / (float)np;
    }

    // ---- tail rows (last CTA, scalar LDG; at most ROWS_T-1 rows) ----
    if (blockIdx.x == G - 1) {
        for (int r = ntiles * ROWS_T + tid; r < n; r += THREADS) {
            float accr = 0.f;
            #pragma unroll
            for (int i = 0; i < 5; i++) {
                float d = __ldg(rrs + r*5 + i) - __ldg(rrsp + r*5 + i);
                accr += c_W5[i] * d * d;
            }
            float rsum = 0.f, lens = 0.f;
            #pragma unroll
            for (int i = 0; i < 9; i++) {
                float d = __ldg(pred + r*9 + i) - __ldg(yobs + r*9 + i);
                rsum += d * d;
                float z = __ldg(nana + r*9 + i);
                lens += (z == z) ? 1.f : 0.f;
            }
            float m0 = __ldg(cov + r*9 + 0), m1 = __ldg(cov + r*9 + 1), m2 = __ldg(cov + r*9 + 2);
            float m3 = __ldg(cov + r*9 + 3), m4 = __ldg(cov + r*9 + 4), m5 = __ldg(cov + r*9 + 5);
            float m6 = __ldg(cov + r*9 + 6), m7 = __ldg(cov + r*9 + 7), m8 = __ldg(cov + r*9 + 8);
            float tr  = m0 + m4 + m8;
            float det = m0 * (m4*m8 - m5*m7) - m1 * (m3*m8 - m5*m6) + m2 * (m3*m7 - m4*m6);
            float accm = 0.f;
            #pragma unroll
            for (int i = 0; i < 3; i++) {
                float d = __ldg(mu + r*3 + i) - MU_PRIOR;
                accm += d * d;
            }
            tot += accr * s_rrs + __fdividef(rsum, lens) * s_obs
                 + ((LOGDET_SA - __logf(det)) + tr * INV49) * s_dk + accm * s_mu;
        }
    }

    // ---- prologue: fill all stages ----
    if (tid == 0) {
        #pragma unroll
        for (int s = 0; s < NST; s++) {
            long long t = (long long)blockIdx.x + (long long)s * G;
            if (t < ntiles) {
                uint32_t sb = s2u(smem) + (uint32_t)s * STAGE_BYTES;
                mbar_expect_tx(mb[s], STAGE_BYTES);
                bulk_cp(sb + OFF_P*4, pred + t*1152, 4608u, mb[s]);
                bulk_cp(sb + OFF_Q*4, yobs + t*1152, 4608u, mb[s]);
                bulk_cp(sb + OFF_Z*4, nana + t*1152, 4608u, mb[s]);
                bulk_cp(sb + OFF_C*4, cov  + t*1152, 4608u, mb[s]);
                bulk_cp(sb + OFF_A*4, rrs  + t*640,  2560u, mb[s]);
                bulk_cp(sb + OFF_E*4, rrsp + t*640,  2560u, mb[s]);
                bulk_cp(sb + OFF_M*4, mu   + t*384,  1536u, mb[s]);
            }
        }
    }

    unsigned phbits = 0;   // per-stage parity bits

    int k = 0;
    for (int t = blockIdx.x; t < ntiles; t += G, k++) {
        const int s = k & (NST - 1);
        const float* sf = smem + s * STAGE_FLOATS;

        mbar_wait(mb[s], (phbits >> s) & 1u);
        phbits ^= (1u << s);

        // ---- flat rrs weighted SSQ: 160 float4 (global idx t*640 ≡ 0 mod 5) ----
        if (tid < 160) {
            const float4* a4 = (const float4*)(sf + OFF_A);
            const float4* e4 = (const float4*)(sf + OFF_E);
            int p = (int)((unsigned)(4 * tid) % 5u);
            tot += wssq(a4[tid], e4[tid], p) * s_rrs;
        }

        // ---- flat mu SSQ: 96 float4 ----
        if (tid < 96) {
            const float4* m4 = (const float4*)(sf + OFF_M);
            float4 m = m4[tid];
            float acc, d;
            d = m.x - MU_PRIOR; acc  = d * d;
            d = m.y - MU_PRIOR; acc += d * d;
            d = m.z - MU_PRIOR; acc += d * d;
            d = m.w - MU_PRIOR; acc += d * d;
            tot += acc * s_mu;
        }

        // ---- row terms: split halves of the block ----
        if (tid < ROWS_T) {
            const float* pr = sf + OFF_P + tid * 9;
            const float* qr = sf + OFF_Q + tid * 9;
            const float* zr = sf + OFF_Z + tid * 9;
            float rsum = 0.f, lens = 0.f;
            #pragma unroll
            for (int i = 0; i < 9; i++) {
                float d = pr[i] - qr[i];
                rsum += d * d;
                float z = zr[i];
                lens += (z == z) ? 1.f : 0.f;
            }
            tot += __fdividef(rsum, lens) * s_obs;
        } else {
            const float* cm = sf + OFF_C + (tid - ROWS_T) * 9;
            float m0 = cm[0], m1 = cm[1], m2 = cm[2];
            float m3 = cm[3], m4 = cm[4], m5 = cm[5];
            float m6 = cm[6], m7 = cm[7], m8 = cm[8];
            float tr  = m0 + m4 + m8;
            float det = m0 * (m4*m8 - m5*m7) - m1 * (m3*m8 - m5*m6) + m2 * (m3*m7 - m4*m6);
            tot += ((LOGDET_SA - __logf(det)) + tr * INV49) * s_dk;
        }

        __syncthreads();   // everyone done reading stage s

        // ---- refill stage s with tile t + NST*G ----
        if (tid == 0) {
            long long tn = (long long)t + (long long)NST * G;
            if (tn < ntiles) {
                uint32_t sb = s2u(smem) + (uint32_t)s * STAGE_BYTES;
                mbar_expect_tx(mb[s], STAGE_BYTES);
                bulk_cp(sb + OFF_P*4, pred + tn*1152, 4608u, mb[s]);
                bulk_cp(sb + OFF_Q*4, yobs + tn*1152, 4608u, mb[s]);
                bulk_cp(sb + OFF_Z*4, nana + tn*1152, 4608u, mb[s]);
                bulk_cp(sb + OFF_C*4, cov  + tn*1152, 4608u, mb[s]);
                bulk_cp(sb + OFF_A*4, rrs  + tn*640,  2560u, mb[s]);
                bulk_cp(sb + OFF_E*4, rrsp + tn*640,  2560u, mb[s]);
                bulk_cp(sb + OFF_M*4, mu   + tn*384,  1536u, mb[s]);
            }
        }
    }

    // ---- block reduction + grid finalize ----
    #pragma unroll
    for (int o = 16; o > 0; o >>= 1) tot += __shfl_down_sync(0xffffffffu, tot, o);
    int lane = tid & 31;
    int wid  = tid >> 5;
    if (lane == 0) wsum[wid] = tot;
    __syncthreads();
    if (wid == 0) {
        float v = (lane < 8) ? wsum[lane] : 0.f;
        #pragma unroll
        for (int o = 4; o > 0; o >>= 1) v += __shfl_down_sync(0xffffffffu, v, o);
        if (lane == 0) {
            atomicAdd(&g_partial, v);
            __threadfence();
            unsigned c = atomicAdd(&g_count, 1u);
            if (c == gridDim.x - 1u) {
                __threadfence();
                float total = atomicExch(&g_partial, 0.f);  // read + reset for replay
                out[0] = total;
                g_count = 0u;
            }
        }
    }
}

extern "C" void kernel_launch(void* const* d_in, const int* in_sizes, int n_in,
                              void* d_out, int out_size)
{
    const float* pred = (const float*)d_in[0];
    const float* yobs = (const float*)d_in[1];
    const float* rrs  = (const float*)d_in[2];
    const float* rrsp = (const float*)d_in[3];
    const float* nana = (const float*)d_in[4];
    const float* cov  = (const float*)d_in[5];
    const float* mu   = (const float*)d_in[6];
    const float* prm  = (const float*)d_in[7];
    float* out = (float*)d_out;

    int n  = in_sizes[0] / 9;
    int np = in_sizes[7];
    int ntiles = n / ROWS_T;                 // full 128-row tiles; tail via LDG

    int dev = 0, sms = 148;
    cudaGetDevice(&dev);
    cudaDeviceGetAttribute(&sms, cudaDevAttrMultiProcessorCount, dev);
    int nblocks = sms * 2;
    if (nblocks > ntiles && ntiles > 0) nblocks = ntiles;
    if (nblocks < 1) nblocks = 1;

    size_t shmem = (size_t)NST * STAGE_BYTES;   // 100,352 B
    cudaFuncSetAttribute(loss_kernel,
                         cudaFuncAttributeMaxDynamicSharedMemorySize, (int)shmem);

    double dn = (double)n;
    float s_rrs = (float)(1.0 / (5.0 * dn));
    float s_obs = (float)(10.0 / dn);
    float s_dk  = (float)(0.5 / dn);
    float s_mu  = (float)(0.5 / (4.9 * 3.0 * dn));

    loss_kernel<<<nblocks, THREADS, shmem>>>(pred, yobs, rrs, rrsp, nana, cov, mu,
                                             prm, out, n, ntiles, np,
                                             s_rrs, s_obs, s_dk, s_mu);
}